// round 10
// baseline (speedup 1.0000x reference)
#include <cuda_runtime.h>
#include <cuda_fp16.h>
#include <cstdint>

// Conv2D 3x3 SAME stride-1 via fused Winograd F(2x2,3x3) + mma.sync.m16n8k16.f16.
// x [16,128,128,64] NHWC fp32, w [3,3,64,128] HWIO, bias [128] -> out fp32.
// Round-10: 512 threads, warp tile 16 tiles x 32 couts -> Y[64]+m[16] regs/thread
// (was Y[128]+m[32] at 255 regs with spills). Same algorithm/layouts as round 9.

#define CH 128
#define CW 128
#define CIN 64
#define COUT 128
#define NB 16

// U: [16 pos][128 co][64 ci] fp16, 128B rows, XOR-16B swizzle (B-operand layout)
__device__ __align__(16) uint32_t g_wu[16 * 128 * 32];

// smem (bytes):
//  [0, 46336)        input fp16 [c2 0..31][h 0..9][w 0..33] half2; plane 362 w, row 36 w
//  [46336, 177408)   V: 16 pos planes x (64 tiles x 128 B, swizzled)
//  [177408, 226560)  U: 3 x 16384 B buffers
#define SM_V 46336
#define SM_U 177408
#define SMEM_BYTES 226560

#define MMA_F16(c, a, b0, b1) \
    asm volatile("mma.sync.aligned.m16n8k16.row.col.f32.f16.f16.f32 " \
        "{%0,%1,%2,%3}, {%4,%5,%6,%7}, {%8,%9}, {%0,%1,%2,%3};" \
        : "+f"((c)[0]), "+f"((c)[1]), "+f"((c)[2]), "+f"((c)[3]) \
        : "r"((a)[0]), "r"((a)[1]), "r"((a)[2]), "r"((a)[3]), \
          "r"(b0), "r"(b1))

#define LDSM4(r0, r1, r2, r3, addr) \
    asm volatile("ldmatrix.sync.aligned.m8n8.x4.shared.b16 {%0,%1,%2,%3}, [%4];" \
        : "=r"(r0), "=r"(r1), "=r"(r2), "=r"(r3) : "r"(addr))

static __device__ __forceinline__ uint32_t smem_u32(const void* p) {
    uint32_t a;
    asm("{ .reg .u64 t; cvta.to.shared.u64 t, %1; cvt.u32.u64 %0, t; }" : "=r"(a) : "l"(p));
    return a;
}
static __device__ __forceinline__ void cp16(uint32_t dst, const void* src) {
    asm volatile("cp.async.ca.shared.global [%0], [%1], 16;"
                 :: "r"(dst), "l"(src) : "memory");
}
static __device__ __forceinline__ uint32_t pack2(float lo, float hi) {
    __half2 h = __floats2half2_rn(lo, hi);
    return *(uint32_t*)&h;
}
static __device__ __forceinline__ void st32(uint32_t addr, uint32_t v) {
    asm volatile("st.shared.b32 [%0], %1;" :: "r"(addr), "r"(v) : "memory");
}
static __device__ __forceinline__ float2 f2add(float2 a, float2 b) {
    return make_float2(a.x + b.x, a.y + b.y);
}
static __device__ __forceinline__ float2 f2sub(float2 a, float2 b) {
    return make_float2(a.x - b.x, a.y - b.y);
}

// ---- weight transform: U = G g G^T per (ci,co), fp32, stored fp16 swizzled ----
__global__ void wino_w_kernel(const float* __restrict__ wt) {
    const int id = blockIdx.x * 256 + threadIdx.x;
    if (id >= CIN * COUT) return;
    const int co = id & 127;
    const int ci = id >> 7;
    float g[3][3];
#pragma unroll
    for (int a = 0; a < 3; ++a)
#pragma unroll
        for (int b = 0; b < 3; ++b)
            g[a][b] = wt[((a * 3 + b) * CIN + ci) * COUT + co];
    float u[4][3];
#pragma unroll
    for (int j = 0; j < 3; ++j) {
        u[0][j] = g[0][j];
        u[1][j] = 0.5f * (g[0][j] + g[1][j] + g[2][j]);
        u[2][j] = 0.5f * (g[0][j] - g[1][j] + g[2][j]);
        u[3][j] = g[2][j];
    }
    __half* gw = (__half*)g_wu;
#pragma unroll
    for (int xi = 0; xi < 4; ++xi) {
        float Uv[4];
        Uv[0] = u[xi][0];
        Uv[1] = 0.5f * (u[xi][0] + u[xi][1] + u[xi][2]);
        Uv[2] = 0.5f * (u[xi][0] - u[xi][1] + u[xi][2]);
        Uv[3] = u[xi][2];
#pragma unroll
        for (int nu = 0; nu < 4; ++nu) {
            const int pos = xi * 4 + nu;
            const int idx = (pos * COUT + co) * 64 + (((ci >> 3) ^ (co & 7)) << 3) + (ci & 7);
            gw[idx] = __float2half(Uv[nu]);
        }
    }
}

// ---- main fused kernel ----
__global__ __launch_bounds__(512, 1)
void wino_main_kernel(const float* __restrict__ x,
                      const float* __restrict__ bias,
                      float* __restrict__ out) {
    extern __shared__ uint32_t smem[];
    const uint32_t sb = smem_u32(smem);

    const int tid  = threadIdx.x;
    const int wid  = tid >> 5;
    const int lane = tid & 31;

    const int bx = blockIdx.x;
    const int n  = bx >> 6;
    const int rr = bx & 63;
    const int x0 = (rr & 3) << 5;       // 32-px strip
    const int y0 = (rr >> 2) << 3;      // 8-px rows

    // ---- prefetch U0, U1 ----
#pragma unroll
    for (int i = 0; i < 2; ++i) {
        const int c = tid + i * 512;
        cp16(sb + SM_U + c * 16, g_wu + c * 4);
    }
    asm volatile("cp.async.commit_group;");
#pragma unroll
    for (int i = 0; i < 2; ++i) {
        const int c = tid + i * 512;
        cp16(sb + SM_U + 16384 + c * 16, g_wu + 4096 + c * 4);
    }
    asm volatile("cp.async.commit_group;");

    // ---- stage input region (34 w x 10 h x 64 c), fp32 -> fp16 [c2][h][w] ----
    const float* xb = x + (size_t)n * CH * CW * CIN;
#pragma unroll
    for (int i = 0; i < 22; ++i) {
        const int idx = tid + i * 512;
        if (idx < 10880) {
            const int c2 = idx & 31;
            const int hw = idx >> 5;
            const int h = (hw * 965) >> 15;       // hw / 34
            const int w = hw - h * 34;
            const int gy = y0 - 1 + h;
            const int gx = x0 - 1 + w;
            uint32_t v = 0;
            if ((unsigned)gy < 128u && (unsigned)gx < 128u) {
                const float2 f = *(const float2*)(xb + (((size_t)gy * CW + gx) << 6) + (c2 << 1));
                v = pack2(f.x, f.y);
            }
            smem[c2 * 362 + h * 36 + w] = v;
        }
    }
    __syncthreads();

    // ---- input transform: V = B^T d B per (tile, channel-pair), fp32 math ----
    {
        const int c2 = tid & 31;
        const int tb = tid >> 5;                  // 0..15
        const uint32_t vlane = ((((c2 >> 2)) << 4) + ((c2 & 3) << 2));
#pragma unroll
        for (int it = 0; it < 4; ++it) {
            const int tile = tb + (it << 4);
            const int ty = tile >> 4, tx = tile & 15;
            const uint32_t* ip = smem + c2 * 362 + (ty * 2) * 36 + tx * 2;
            float2 d[4][4];
#pragma unroll
            for (int i2 = 0; i2 < 4; ++i2) {
                const uint2 ra = *(const uint2*)(ip + i2 * 36);
                const uint2 rb = *(const uint2*)(ip + i2 * 36 + 2);
                d[i2][0] = __half22float2(*(__half2*)&ra.x);
                d[i2][1] = __half22float2(*(__half2*)&ra.y);
                d[i2][2] = __half22float2(*(__half2*)&rb.x);
                d[i2][3] = __half22float2(*(__half2*)&rb.y);
            }
            float2 t[4][4];
#pragma unroll
            for (int j = 0; j < 4; ++j) {
                t[0][j] = f2sub(d[0][j], d[2][j]);
                t[1][j] = f2add(d[1][j], d[2][j]);
                t[2][j] = f2sub(d[2][j], d[1][j]);
                t[3][j] = f2sub(d[1][j], d[3][j]);
            }
            const uint32_t vb = sb + SM_V + tile * 128
                              + (vlane ^ ((uint32_t)(tile & 7) << 4));
#pragma unroll
            for (int i2 = 0; i2 < 4; ++i2) {
                const float2 v0 = f2sub(t[i2][0], t[i2][2]);
                const float2 v1 = f2add(t[i2][1], t[i2][2]);
                const float2 v2 = f2sub(t[i2][2], t[i2][1]);
                const float2 v3 = f2sub(t[i2][1], t[i2][3]);
                st32(vb + (i2 * 4 + 0) * 8192, pack2(v0.x, v0.y));
                st32(vb + (i2 * 4 + 1) * 8192, pack2(v1.x, v1.y));
                st32(vb + (i2 * 4 + 2) * 8192, pack2(v2.x, v2.y));
                st32(vb + (i2 * 4 + 3) * 8192, pack2(v3.x, v3.y));
            }
        }
    }
    // (V visibility covered by the p=0 __syncthreads below)

    // ---- 16 position GEMMs + in-register output transform ----
    const int wm = wid & 3;              // tile-row block (16 tiles each)
    const int wn = wid >> 2;             // cout quarter (32 couts each)

    const int rowA = (wm << 4) + (lane & 7) + (((lane >> 3) & 1) << 3);
    const uint32_t aRow = sb + SM_V + rowA * 128;
    const int xr  = lane & 7;
    const int ghi = (lane >> 4) & 1;
    const int kbit = (lane >> 3) & 1;
    const int co_lane = xr + ((lane >> 4) << 3);
    const uint32_t bco = (uint32_t)((wn * 32 + co_lane) * 128);

    float Y[4][16];
#pragma unroll
    for (int q = 0; q < 16; ++q) { Y[0][q] = 0.f; Y[1][q] = 0.f; Y[2][q] = 0.f; Y[3][q] = 0.f; }

#pragma unroll 1
    for (int p = 0; p < 16; ++p) {
        if (p < 15) asm volatile("cp.async.wait_group 1;" ::: "memory");
        else        asm volatile("cp.async.wait_group 0;" ::: "memory");
        __syncthreads();
        if (p < 14) {
            const uint32_t dstb = sb + SM_U + ((p + 2) % 3) * 16384;
            const uint32_t* srcb = g_wu + (p + 2) * 4096;
#pragma unroll
            for (int i = 0; i < 2; ++i) {
                const int c = tid + i * 512;
                cp16(dstb + c * 16, srcb + c * 4);
            }
            asm volatile("cp.async.commit_group;");
        }

        const uint32_t aPos = aRow + (uint32_t)p * 8192u;
        const uint32_t bb = sb + SM_U + (p % 3) * 16384 + bco;

        float m[4][4];
#pragma unroll
        for (int nb = 0; nb < 4; ++nb)
#pragma unroll
            for (int q = 0; q < 4; ++q) m[nb][q] = 0.f;

#pragma unroll
        for (int ks = 0; ks < 4; ++ks) {
            uint32_t a[4];
            LDSM4(a[0], a[1], a[2], a[3], aPos + (uint32_t)(((ks * 2 + ghi) ^ xr) << 4));
            const uint32_t swz = (uint32_t)(((ks * 2 + kbit) ^ xr) << 4);
            uint32_t b[8];
            LDSM4(b[0], b[1], b[2], b[3], bb + swz);
            LDSM4(b[4], b[5], b[6], b[7], bb + 2048u + swz);
            MMA_F16(m[0], a, b[0], b[1]);
            MMA_F16(m[1], a, b[2], b[3]);
            MMA_F16(m[2], a, b[4], b[5]);
            MMA_F16(m[3], a, b[6], b[7]);
        }

        // Y += (A^T coeff)(position p) * M ; coeffs in {0,+1,-1}
        const int xi = p >> 2, nu = p & 3;
#pragma unroll
        for (int oi = 0; oi < 2; ++oi) {
#pragma unroll
            for (int oj = 0; oj < 2; ++oj) {
                const int ci = (oi == 0) ? ((xi < 3) ? 1 : 0)
                                         : ((xi == 0) ? 0 : (xi == 1 ? 1 : -1));
                const int cj = (oj == 0) ? ((nu < 3) ? 1 : 0)
                                         : ((nu == 0) ? 0 : (nu == 1 ? 1 : -1));
                const int cc = ci * cj;
                if (cc == 1) {
#pragma unroll
                    for (int nb = 0; nb < 4; ++nb)
#pragma unroll
                        for (int q = 0; q < 4; ++q)
                            Y[oi * 2 + oj][nb * 4 + q] += m[nb][q];
                } else if (cc == -1) {
#pragma unroll
                    for (int nb = 0; nb < 4; ++nb)
#pragma unroll
                        for (int q = 0; q < 4; ++q)
                            Y[oi * 2 + oj][nb * 4 + q] -= m[nb][q];
                }
            }
        }
    }

    // ---- epilogue: bias + store (2x2 outputs per tile) ----
    const int t4 = lane & 3;
    const int co0 = wn * 32 + t4 * 2;
    float2 bv[4];
#pragma unroll
    for (int nb = 0; nb < 4; ++nb) bv[nb] = *(const float2*)&bias[co0 + nb * 8];

    const int hb = y0 + 2 * wm;
    const int rA = lane >> 2;
#pragma unroll
    for (int th = 0; th < 2; ++th) {
        const int wb = x0 + 2 * (rA + 8 * th);
#pragma unroll
        for (int oi = 0; oi < 2; ++oi) {
#pragma unroll
            for (int oj = 0; oj < 2; ++oj) {
                float* orow = out + ((((size_t)n * CH + (hb + oi)) * CW) + (wb + oj)) * COUT + co0;
#pragma unroll
                for (int nb = 0; nb < 4; ++nb) {
                    float2 v;
                    v.x = Y[oi * 2 + oj][nb * 4 + 2 * th]     + bv[nb].x;
                    v.y = Y[oi * 2 + oj][nb * 4 + 2 * th + 1] + bv[nb].y;
                    *(float2*)&orow[nb * 8] = v;
                }
            }
        }
    }
}

extern "C" void kernel_launch(void* const* d_in, const int* in_sizes, int n_in,
                              void* d_out, int out_size) {
    const float* x    = (const float*)d_in[0];
    const float* wt   = (const float*)d_in[1];
    const float* bias = (const float*)d_in[2];
    float* out = (float*)d_out;

    cudaFuncSetAttribute(wino_main_kernel,
                         cudaFuncAttributeMaxDynamicSharedMemorySize, SMEM_BYTES);

    wino_w_kernel<<<32, 256>>>(wt);
    wino_main_kernel<<<NB * 64, 512, SMEM_BYTES>>>(x, bias, out);
}

// round 11
// speedup vs baseline: 1.2908x; 1.2908x over previous
#include <cuda_runtime.h>
#include <cuda_fp16.h>
#include <cstdint>

// Conv2D 3x3 SAME stride-1, mma.sync.m16n8k16.f16 (fp32 accum).
// (1) cvt+transpose+swizzle w -> fp16 gmem smem-image (tiny kernel),
// (2) main: A staged DIRECTLY from fp32 x (LDG.128 -> cvt -> STS.128, halo
//     zero-fill); B double-buffered per tap via cp.async from the pre-swizzled
//     image; ldmatrix + MMA mainloop. 70.8 KB smem -> 2 CTAs/SM.
// CTA: M=128 (2 out rows x 64-pix strip) x N=128, 256 thr, 8 warps of 32x64.

#define CH 128
#define CW 128
#define CIN 64
#define COUT 128
#define NTAP 9
#define NB 16

#define W_WORDS (NTAP*COUT*32)
__device__ __align__(16) uint32_t g_wh[W_WORDS];

#define APW 36                       // A pixel-row stride in words (144 B)
#define A_PLANE_W (66*APW)           // 66 pixel rows (64 strip + 2 halo)
#define AS_WORDS (4*A_PLANE_W)       // 9504 words
#define B_BYTES 16384                // one tap image
#define SMEM_BYTES (AS_WORDS*4 + 2*B_BYTES)   // 70,784 B -> 2 CTAs/SM

#define MMA_F16(c, a, b0, b1) \
    asm volatile("mma.sync.aligned.m16n8k16.row.col.f32.f16.f16.f32 " \
        "{%0,%1,%2,%3}, {%4,%5,%6,%7}, {%8,%9}, {%0,%1,%2,%3};" \
        : "+f"((c)[0]), "+f"((c)[1]), "+f"((c)[2]), "+f"((c)[3]) \
        : "r"((a)[0]), "r"((a)[1]), "r"((a)[2]), "r"((a)[3]), \
          "r"(b0), "r"(b1))

#define LDSM4(r0, r1, r2, r3, addr) \
    asm volatile("ldmatrix.sync.aligned.m8n8.x4.shared.b16 {%0,%1,%2,%3}, [%4];" \
        : "=r"(r0), "=r"(r1), "=r"(r2), "=r"(r3) : "r"(addr))

static __device__ __forceinline__ uint32_t smem_u32(const void* p) {
    uint32_t a;
    asm("{ .reg .u64 t; cvta.to.shared.u64 t, %1; cvt.u32.u64 %0, t; }" : "=r"(a) : "l"(p));
    return a;
}
static __device__ __forceinline__ void cp16(uint32_t dst, const void* src) {
    asm volatile("cp.async.ca.shared.global [%0], [%1], 16;"
                 :: "r"(dst), "l"(src) : "memory");
}
static __device__ __forceinline__ uint32_t pack2(float lo, float hi) {
    __half2 h = __floats2half2_rn(lo, hi);
    return *(uint32_t*)&h;
}

// ---- pre-kernel: w [tap][k][co] -> fp16 [tap][co][k], XOR-swizzled 16B chunks ----
__global__ void cvt_w_kernel(const float* __restrict__ wt) {
    const int tid = blockIdx.x * blockDim.x + threadIdx.x;
    if (tid >= NTAP * CIN * COUT) return;
    const int co = tid & 127;
    const int k  = (tid >> 7) & 63;
    const int t  = tid >> 13;
    __half* dst = (__half*)g_wh;
    const int half_idx = (t * COUT + co) * 64 + (((k >> 3) ^ (co & 7)) << 3) + (k & 7);
    dst[half_idx] = __float2half(wt[tid]);
}

// ---- main kernel ----
__global__ __launch_bounds__(256, 2)
void conv3x3_db_kernel(const float* __restrict__ x,
                       const float* __restrict__ bias,
                       float* __restrict__ out) {
    extern __shared__ uint32_t smem[];
    const uint32_t sb  = smem_u32(smem);
    const uint32_t sbB = sb + AS_WORDS * 4;

    const int tid  = threadIdx.x;
    const int wid  = tid >> 5;
    const int lane = tid & 31;
    const int gid  = lane >> 2;
    const int t4   = lane & 3;
    const int warp_m = wid >> 1;         // 0..3
    const int warp_n = wid & 1;          // 0..1

    const int bx = blockIdx.x;
    const int n  = bx >> 7;
    const int r  = bx & 127;
    const int h0 = (r >> 1) << 1;        // output rows h0, h0+1
    const int ps = (r & 1) << 6;         // pixel strip base: 0 or 64

    // ---- B tap 0 via cp.async (start it first so it overlaps A staging) ----
#pragma unroll
    for (int i = 0; i < 4; ++i) {
        const int c = tid + i * 256;
        cp16(sbB + c * 16, g_wh + c * 4);
    }
    asm volatile("cp.async.commit_group;");

    // ---- stage A directly from fp32 x: 4 halo planes, 2112 fp16 16B-chunks ----
    const float* xb = x + (size_t)n * CH * CW * CIN;
#pragma unroll
    for (int i = 0; i < 9; ++i) {
        const int c = tid + i * 256;
        if (c < 2112) {
            const int plane = c / 528;           // 66 rows x 8 chunks
            const int rem   = c - plane * 528;
            const int prow  = rem >> 3;
            const int c8    = rem & 7;           // 8-half chunk within row
            const int hr = h0 - 1 + plane;
            const int gp = ps - 1 + prow;
            uint4 tv = make_uint4(0u, 0u, 0u, 0u);
            if (((unsigned)hr < (unsigned)CH) && ((unsigned)gp < (unsigned)CW)) {
                const float4* s = (const float4*)(xb + (((size_t)hr * CW + gp) << 6) + (c8 << 3));
                const float4 a0 = s[0];
                const float4 a1 = s[1];
                tv.x = pack2(a0.x, a0.y); tv.y = pack2(a0.z, a0.w);
                tv.z = pack2(a1.x, a1.y); tv.w = pack2(a1.z, a1.w);
            }
            *(uint4*)((char*)smem + (plane * A_PLANE_W + prow * APW) * 4 + c8 * 16) = tv;
        }
    }

    // ---- accumulators ----
    float acc[2][8][4];
#pragma unroll
    for (int mi = 0; mi < 2; ++mi)
#pragma unroll
        for (int ni = 0; ni < 8; ++ni)
#pragma unroll
            for (int q = 0; q < 4; ++q) acc[mi][ni][q] = 0.0f;

    const int row_sel  = warp_m >> 1;
    const int pix_base = (warp_m & 1) << 5;

    const uint32_t lane_off_a = (uint32_t)((lane & 15) * 144 + (lane >> 4) * 16);
    const int xlane   = lane & 7;
    const int kbit    = (lane >> 3) & 1;
    const int co_lane = xlane + ((lane >> 4) << 3);
    const uint32_t bco = (uint32_t)((warp_n * 64 + co_lane) * 128);

    // ---- mainloop: 9 taps, B double-buffered ----
#pragma unroll 1
    for (int t = 0; t < 9; ++t) {
        asm volatile("cp.async.wait_group 0;" ::: "memory");
        __syncthreads();    // B[t] + (t=0) A visible; buf[(t+1)&1] free

        if (t < 8) {        // stage next tap, overlapped with this tap's MMAs
            const uint32_t dst = sbB + (uint32_t)(((t + 1) & 1) * B_BYTES);
            const uint32_t* src = g_wh + (t + 1) * 4096;
#pragma unroll
            for (int i = 0; i < 4; ++i) {
                const int c = tid + i * 256;
                cp16(dst + c * 16, src + c * 4);
            }
            asm volatile("cp.async.commit_group;");
        }

        const int kh = (t * 11) >> 5;            // t/3
        const int kw = t - kh * 3;
        const uint32_t abase = sb + (uint32_t)((row_sel + kh) * (A_PLANE_W * 4)
                                   + (pix_base + kw) * 144) + lane_off_a;
        const uint32_t bb = sbB + (uint32_t)((t & 1) * B_BYTES) + bco;

#pragma unroll
        for (int ks = 0; ks < 4; ++ks) {
            uint32_t a[2][4];
#pragma unroll
            for (int mi = 0; mi < 2; ++mi)
                LDSM4(a[mi][0], a[mi][1], a[mi][2], a[mi][3],
                      abase + (uint32_t)(mi * 2304 + ks * 32));
            const uint32_t swz = (uint32_t)(((2 * ks + kbit) ^ xlane) << 4);
            uint32_t b[8];
            LDSM4(b[0], b[1], b[2], b[3], bb + swz);
            LDSM4(b[4], b[5], b[6], b[7], bb + 2048u + swz);
            uint32_t c[8];
            LDSM4(c[0], c[1], c[2], c[3], bb + 4096u + swz);
            LDSM4(c[4], c[5], c[6], c[7], bb + 6144u + swz);
#pragma unroll
            for (int mi = 0; mi < 2; ++mi) {
                MMA_F16(acc[mi][0], a[mi], b[0], b[1]);
                MMA_F16(acc[mi][1], a[mi], b[2], b[3]);
                MMA_F16(acc[mi][2], a[mi], b[4], b[5]);
                MMA_F16(acc[mi][3], a[mi], b[6], b[7]);
                MMA_F16(acc[mi][4], a[mi], c[0], c[1]);
                MMA_F16(acc[mi][5], a[mi], c[2], c[3]);
                MMA_F16(acc[mi][6], a[mi], c[4], c[5]);
                MMA_F16(acc[mi][7], a[mi], c[6], c[7]);
            }
        }
    }

    // ---- epilogue: bias + store ----
    const int hrow = h0 + row_sel;
    float* orow = out + (((size_t)n * CH + hrow) * CW + ps) * COUT;
    const int co0 = warp_n * 64 + t4 * 2;

    float2 bv[8];
#pragma unroll
    for (int ni = 0; ni < 8; ++ni)
        bv[ni] = *(const float2*)&bias[co0 + ni * 8];

#pragma unroll
    for (int mi = 0; mi < 2; ++mi) {
        const int p0 = pix_base + mi * 16 + gid;
#pragma unroll
        for (int ni = 0; ni < 8; ++ni) {
            const int cout = co0 + ni * 8;
            float2 v0, v1;
            v0.x = acc[mi][ni][0] + bv[ni].x;
            v0.y = acc[mi][ni][1] + bv[ni].y;
            v1.x = acc[mi][ni][2] + bv[ni].x;
            v1.y = acc[mi][ni][3] + bv[ni].y;
            *(float2*)&orow[(size_t)p0 * COUT + cout]       = v0;
            *(float2*)&orow[(size_t)(p0 + 8) * COUT + cout] = v1;
        }
    }
}

extern "C" void kernel_launch(void* const* d_in, const int* in_sizes, int n_in,
                              void* d_out, int out_size) {
    const float* x    = (const float*)d_in[0];
    const float* wt   = (const float*)d_in[1];
    const float* bias = (const float*)d_in[2];
    float* out = (float*)d_out;

    cudaFuncSetAttribute(conv3x3_db_kernel,
                         cudaFuncAttributeMaxDynamicSharedMemorySize, SMEM_BYTES);

    cvt_w_kernel<<<(NTAP * CIN * COUT + 255) / 256, 256>>>(wt);

    dim3 grid(NB * CH);                          // 2048 CTAs
    conv3x3_db_kernel<<<grid, 256, SMEM_BYTES>>>(x, bias, out);
}

// round 13
// speedup vs baseline: 1.3561x; 1.0506x over previous
#include <cuda_runtime.h>
#include <cuda_fp16.h>
#include <cstdint>

// Conv2D 3x3 SAME stride-1, mma.sync.m16n8k16.f16 (fp32 accum).
// Round-12 (resubmit; prior run died to a container infra failure, not the kernel):
// 64x64 warp tiles (128 B LDSM per MMA vs 192) to relieve the L1 pipe.
// CTA: M=128 (2 out rows x 64-pix strip) x N=128, 128 thr, 4 warps of 64x64,
// 2 CTAs/SM (regs <=256 each). A staged from fp32 x in-prologue; B per-tap
// double-buffered cp.async from pre-swizzled fp16 image.

#define CH 128
#define CW 128
#define CIN 64
#define COUT 128
#define NTAP 9
#define NB 16

#define W_WORDS (NTAP*COUT*32)
__device__ __align__(16) uint32_t g_wh[W_WORDS];

#define APW 36                       // A pixel-row stride in words (144 B)
#define A_PLANE_W (66*APW)           // 66 pixel rows (64 strip + 2 halo)
#define AS_WORDS (4*A_PLANE_W)       // 9504 words
#define B_BYTES 16384                // one tap image
#define SMEM_BYTES (AS_WORDS*4 + 2*B_BYTES)   // 70,784 B -> 2 CTAs/SM

#define MMA_F16(c, a, b0, b1) \
    asm volatile("mma.sync.aligned.m16n8k16.row.col.f32.f16.f16.f32 " \
        "{%0,%1,%2,%3}, {%4,%5,%6,%7}, {%8,%9}, {%0,%1,%2,%3};" \
        : "+f"((c)[0]), "+f"((c)[1]), "+f"((c)[2]), "+f"((c)[3]) \
        : "r"((a)[0]), "r"((a)[1]), "r"((a)[2]), "r"((a)[3]), \
          "r"(b0), "r"(b1))

#define LDSM4(r0, r1, r2, r3, addr) \
    asm volatile("ldmatrix.sync.aligned.m8n8.x4.shared.b16 {%0,%1,%2,%3}, [%4];" \
        : "=r"(r0), "=r"(r1), "=r"(r2), "=r"(r3) : "r"(addr))

static __device__ __forceinline__ uint32_t smem_u32(const void* p) {
    uint32_t a;
    asm("{ .reg .u64 t; cvta.to.shared.u64 t, %1; cvt.u32.u64 %0, t; }" : "=r"(a) : "l"(p));
    return a;
}
static __device__ __forceinline__ void cp16(uint32_t dst, const void* src) {
    asm volatile("cp.async.ca.shared.global [%0], [%1], 16;"
                 :: "r"(dst), "l"(src) : "memory");
}
static __device__ __forceinline__ uint32_t pack2(float lo, float hi) {
    __half2 h = __floats2half2_rn(lo, hi);
    return *(uint32_t*)&h;
}

// ---- pre-kernel: w [tap][k][co] -> fp16 [tap][co][k], XOR-swizzled 16B chunks ----
__global__ void cvt_w_kernel(const float* __restrict__ wt) {
    const int tid = blockIdx.x * blockDim.x + threadIdx.x;
    if (tid >= NTAP * CIN * COUT) return;
    const int co = tid & 127;
    const int k  = (tid >> 7) & 63;
    const int t  = tid >> 13;
    __half* dst = (__half*)g_wh;
    const int half_idx = (t * COUT + co) * 64 + (((k >> 3) ^ (co & 7)) << 3) + (k & 7);
    dst[half_idx] = __float2half(wt[tid]);
}

// ---- main kernel ----
__global__ __launch_bounds__(128, 2)
void conv3x3_w64_kernel(const float* __restrict__ x,
                        const float* __restrict__ bias,
                        float* __restrict__ out) {
    extern __shared__ uint32_t smem[];
    const uint32_t sb  = smem_u32(smem);
    const uint32_t sbB = sb + AS_WORDS * 4;

    const int tid  = threadIdx.x;
    const int wid  = tid >> 5;
    const int lane = tid & 31;
    const int gid  = lane >> 2;
    const int t4   = lane & 3;
    const int warp_m = wid >> 1;         // 0..1 : output row
    const int warp_n = wid & 1;          // 0..1 : cout half

    const int bx = blockIdx.x;
    const int n  = bx >> 7;
    const int r  = bx & 127;
    const int h0 = (r >> 1) << 1;        // output rows h0, h0+1
    const int ps = (r & 1) << 6;         // pixel strip base: 0 or 64

    // ---- B tap 0 via cp.async first (overlaps A staging) ----
#pragma unroll
    for (int i = 0; i < 8; ++i) {
        const int c = tid + i * 128;
        cp16(sbB + c * 16, g_wh + c * 4);
    }
    asm volatile("cp.async.commit_group;");

    // ---- stage A directly from fp32 x: 4 halo planes, 2112 fp16 16B-chunks ----
    const float* xb = x + (size_t)n * CH * CW * CIN;
#pragma unroll
    for (int i = 0; i < 17; ++i) {
        const int c = tid + i * 128;
        if (c < 2112) {
            const int plane = c / 528;           // 66 rows x 8 chunks
            const int rem   = c - plane * 528;
            const int prow  = rem >> 3;
            const int c8    = rem & 7;           // 8-half chunk within row
            const int hr = h0 - 1 + plane;
            const int gp = ps - 1 + prow;
            uint4 tv = make_uint4(0u, 0u, 0u, 0u);
            if (((unsigned)hr < (unsigned)CH) && ((unsigned)gp < (unsigned)CW)) {
                const float4* s = (const float4*)(xb + (((size_t)hr * CW + gp) << 6) + (c8 << 3));
                const float4 a0 = s[0];
                const float4 a1 = s[1];
                tv.x = pack2(a0.x, a0.y); tv.y = pack2(a0.z, a0.w);
                tv.z = pack2(a1.x, a1.y); tv.w = pack2(a1.z, a1.w);
            }
            *(uint4*)((char*)smem + (plane * A_PLANE_W + prow * APW) * 4 + c8 * 16) = tv;
        }
    }

    // ---- accumulators: warp tile 64 px x 64 couts ----
    float acc[4][8][4];
#pragma unroll
    for (int mi = 0; mi < 4; ++mi)
#pragma unroll
        for (int ni = 0; ni < 8; ++ni)
#pragma unroll
            for (int q = 0; q < 4; ++q) acc[mi][ni][q] = 0.0f;

    const uint32_t lane_off_a = (uint32_t)((lane & 15) * 144 + (lane >> 4) * 16);
    const int xlane   = lane & 7;
    const int kbit    = (lane >> 3) & 1;
    const int co_lane = xlane + ((lane >> 4) << 3);
    const uint32_t bco = (uint32_t)((warp_n * 64 + co_lane) * 128);

    // ---- mainloop: 9 taps, B double-buffered ----
#pragma unroll 1
    for (int t = 0; t < 9; ++t) {
        asm volatile("cp.async.wait_group 0;" ::: "memory");
        __syncthreads();    // B[t] + (t=0) A visible; buf[(t+1)&1] free

        if (t < 8) {        // stage next tap, overlapped with this tap's MMAs
            const uint32_t dst = sbB + (uint32_t)(((t + 1) & 1) * B_BYTES);
            const uint32_t* src = g_wh + (t + 1) * 4096;
#pragma unroll
            for (int i = 0; i < 8; ++i) {
                const int c = tid + i * 128;
                cp16(dst + c * 16, src + c * 4);
            }
            asm volatile("cp.async.commit_group;");
        }

        const int kh = (t * 11) >> 5;            // t/3
        const int kw = t - kh * 3;
        // strip pixel p (0..63) lives at plane row p+1; output pixel p needs
        // input pixel p+kw-1 = plane row p+kw.
        const uint32_t abase = sb + (uint32_t)((warp_m + kh) * (A_PLANE_W * 4)
                                   + kw * 144) + lane_off_a;
        const uint32_t bb = sbB + (uint32_t)((t & 1) * B_BYTES) + bco;

#pragma unroll
        for (int ks = 0; ks < 4; ++ks) {
            uint32_t a[4][4];
#pragma unroll
            for (int mi = 0; mi < 4; ++mi)
                LDSM4(a[mi][0], a[mi][1], a[mi][2], a[mi][3],
                      abase + (uint32_t)(mi * 2304 + ks * 32));
            const uint32_t swz = (uint32_t)(((2 * ks + kbit) ^ xlane) << 4);
            uint32_t b[8];
            LDSM4(b[0], b[1], b[2], b[3], bb + swz);
            LDSM4(b[4], b[5], b[6], b[7], bb + 2048u + swz);
            uint32_t c[8];
            LDSM4(c[0], c[1], c[2], c[3], bb + 4096u + swz);
            LDSM4(c[4], c[5], c[6], c[7], bb + 6144u + swz);
#pragma unroll
            for (int mi = 0; mi < 4; ++mi) {
                MMA_F16(acc[mi][0], a[mi], b[0], b[1]);
                MMA_F16(acc[mi][1], a[mi], b[2], b[3]);
                MMA_F16(acc[mi][2], a[mi], b[4], b[5]);
                MMA_F16(acc[mi][3], a[mi], b[6], b[7]);
                MMA_F16(acc[mi][4], a[mi], c[0], c[1]);
                MMA_F16(acc[mi][5], a[mi], c[2], c[3]);
                MMA_F16(acc[mi][6], a[mi], c[4], c[5]);
                MMA_F16(acc[mi][7], a[mi], c[6], c[7]);
            }
        }
    }

    // ---- epilogue: bias + store (64 px x 64 couts per warp) ----
    const int hrow = h0 + warp_m;
    float* orow = out + (((size_t)n * CH + hrow) * CW + ps) * COUT;
    const int co0 = warp_n * 64 + t4 * 2;

    float2 bv[8];
#pragma unroll
    for (int ni = 0; ni < 8; ++ni)
        bv[ni] = *(const float2*)&bias[co0 + ni * 8];

#pragma unroll
    for (int mi = 0; mi < 4; ++mi) {
        const int p0 = mi * 16 + gid;
#pragma unroll
        for (int ni = 0; ni < 8; ++ni) {
            const int cout = co0 + ni * 8;
            float2 v0, v1;
            v0.x = acc[mi][ni][0] + bv[ni].x;
            v0.y = acc[mi][ni][1] + bv[ni].y;
            v1.x = acc[mi][ni][2] + bv[ni].x;
            v1.y = acc[mi][ni][3] + bv[ni].y;
            *(float2*)&orow[(size_t)p0 * COUT + cout]       = v0;
            *(float2*)&orow[(size_t)(p0 + 8) * COUT + cout] = v1;
        }
    }
}

extern "C" void kernel_launch(void* const* d_in, const int* in_sizes, int n_in,
                              void* d_out, int out_size) {
    const float* x    = (const float*)d_in[0];
    const float* wt   = (const float*)d_in[1];
    const float* bias = (const float*)d_in[2];
    float* out = (float*)d_out;

    cudaFuncSetAttribute(conv3x3_w64_kernel,
                         cudaFuncAttributeMaxDynamicSharedMemorySize, SMEM_BYTES);

    cvt_w_kernel<<<(NTAP * CIN * COUT + 255) / 256, 256>>>(wt);

    dim3 grid(NB * CH);                          // 2048 CTAs
    conv3x3_w64_kernel<<<grid, 128, SMEM_BYTES>>>(x, bias, out);
}